// round 7
// baseline (speedup 1.0000x reference)
#include <cuda_runtime.h>
#include <cuda_bf16.h>
#include <cuda_fp16.h>
#include <cstdint>

#define NB    4
#define SQ    2048
#define PAST  2048
#define DIN   2048
#define DH    2048
#define DFF   8192
#define KVLEN (PAST + SQ)   // 4096

// ======================= device scratch (no allocation) ======================
__device__ float g_scores[(long long)NB * SQ * KVLEN];            // 134 MB
__device__ __nv_bfloat16 g_xs [(long long)NB*SQ * 3*DIN];
__device__ __nv_bfloat16 g_qs [(long long)NB*SQ * 3*DH];
__device__ __nv_bfloat16 g_ks [(long long)NB*KVLEN * 3*DH];
__device__ __nv_bfloat16 g_wqs[(long long)DH * 3*DIN];
__device__ __nv_bfloat16 g_wks[(long long)DH * 3*DIN];
__device__ __half g_xh   [(long long)NB*SQ * DIN];
__device__ __half g_wvh  [(long long)DH * DIN];
__device__ __half g_wffh [(long long)DFF * DH];
__device__ __half g_wouth[(long long)DH * DFF];
__device__ __half g_vth  [(long long)NB * DH * KVLEN];
__device__ __half g_attnh[(long long)NB * SQ * KVLEN];
__device__ __half g_ctxh [(long long)NB * SQ * DH];
__device__ __half g_ffh  [(long long)NB * SQ * DFF];

// ======================= helpers =============================================
__device__ __forceinline__ uint32_t smem_u32(const void* p) {
    uint32_t a;
    asm("{ .reg .u64 t; cvta.to.shared.u64 t, %1; cvt.u32.u64 %0, t; }" : "=r"(a) : "l"(p));
    return a;
}
__device__ __forceinline__ void ldm4(uint32_t* f, uint32_t a) {
    asm volatile("ldmatrix.sync.aligned.m8n8.x4.shared.b16 {%0,%1,%2,%3}, [%4];"
                 : "=r"(f[0]), "=r"(f[1]), "=r"(f[2]), "=r"(f[3]) : "r"(a));
}
template<int DT>   // 0 = bf16, 1 = f16
__device__ __forceinline__ void mma_op(float* c, const uint32_t* a, uint32_t b0, uint32_t b1) {
    if (DT == 0)
        asm volatile("mma.sync.aligned.m16n8k16.row.col.f32.bf16.bf16.f32 "
                     "{%0,%1,%2,%3}, {%4,%5,%6,%7}, {%8,%9}, {%0,%1,%2,%3};"
                     : "+f"(c[0]), "+f"(c[1]), "+f"(c[2]), "+f"(c[3])
                     : "r"(a[0]), "r"(a[1]), "r"(a[2]), "r"(a[3]), "r"(b0), "r"(b1));
    else
        asm volatile("mma.sync.aligned.m16n8k16.row.col.f32.f16.f16.f32 "
                     "{%0,%1,%2,%3}, {%4,%5,%6,%7}, {%8,%9}, {%0,%1,%2,%3};"
                     : "+f"(c[0]), "+f"(c[1]), "+f"(c[2]), "+f"(c[3])
                     : "r"(a[0]), "r"(a[1]), "r"(a[2]), "r"(a[3]), "r"(b0), "r"(b1));
}
__device__ __forceinline__ unsigned short bf16bits(float f) {
    __nv_bfloat16 h = __float2bfloat16(f);
    return *reinterpret_cast<unsigned short*>(&h);
}
__device__ __forceinline__ float bf16val(unsigned short u) {
    __nv_bfloat16 h = *reinterpret_cast<__nv_bfloat16*>(&u);
    return __bfloat162float(h);
}
__device__ __forceinline__ uint32_t swz(int r, int j) {   // 16B seg j in 64B row r
    return (uint32_t)(r * 64 + ((j ^ ((r >> 1) & 3)) << 4));
}
#define CP16(dst, src) asm volatile("cp.async.ca.shared.global [%0], [%1], 16;" :: "r"(dst), "l"(src) : "memory")
#define CP_COMMIT()    asm volatile("cp.async.commit_group;" ::: "memory")

// ======================= GEMM: C[M,N] = A[M,K]·B[N,K]^T =====================
// CTA tile 128x256x32. 8 warps in 2(M) x 4(N); warp tile 64x64.
// 4-stage cp.async pipeline, dynamic smem: A 4x8KB @0, B 4x16KB @32KB (96KB).
// Outputs (nullable): C fp32; sA3 bf16 3-seg (hi,hi,lo) stride 3N; sH fp16 stride N.
#define ASTG 8192
#define BSTG 16384
#define BOFF 32768
#define SMEM_GEMM (BOFF + 4 * BSTG)   // 98304

template<int DT>
__global__ void __launch_bounds__(256, 1)
gemm_tc(const uint16_t* __restrict__ A, const uint16_t* __restrict__ B,
        const float* __restrict__ bias, float* __restrict__ C,
        __nv_bfloat16* __restrict__ sA3, __half* __restrict__ sH,
        int N, long long Kp,
        long long aBatch, long long bBatch,
        int cBatchRows, int cRowOff)
{
    extern __shared__ __align__(16) uint8_t smem[];
    const uint32_t sb = smem_u32(smem);

    const int tid = threadIdx.x;
    const int wid = tid >> 5;
    const int lid = tid & 31;
    const long long bn0 = (long long)blockIdx.x * 256;
    const long long bm0 = (long long)blockIdx.y * 128;

    A += (long long)blockIdx.z * aBatch + bm0 * Kp;
    B += (long long)blockIdx.z * bBatch + bn0 * Kp;

    // loaders: A 512 segs (2/thread), B 1024 segs (4/thread)
    const int lrA0 = tid >> 2,        ljA = tid & 3;
    const int lrA1 = lrA0 + 64;
    const uint16_t* aG0 = A + (long long)lrA0 * Kp + ljA * 8;
    const uint16_t* aG1 = A + (long long)lrA1 * Kp + ljA * 8;
    const uint32_t saA0 = swz(lrA0, ljA), saA1 = swz(lrA1, ljA);
    const uint16_t* bG[4];
    uint32_t saB[4];
#pragma unroll
    for (int j = 0; j < 4; j++) {
        const int r = (tid >> 2) + 64 * j;
        bG[j] = B + (long long)r * Kp + ljA * 8;
        saB[j] = swz(r, ljA);
    }

    const int nT = (int)(Kp >> 5);

    auto ldStage = [&](int slot, int chunk) {
        const long long o = (long long)chunk * 32;
        const uint32_t ab = sb + slot * ASTG;
        const uint32_t bb = sb + BOFF + slot * BSTG;
        CP16(ab + saA0, aG0 + o);
        CP16(ab + saA1, aG1 + o);
#pragma unroll
        for (int j = 0; j < 4; j++) CP16(bb + saB[j], bG[j] + o);
        CP_COMMIT();
    };
    ldStage(0, 0);
    ldStage(1, 1);
    ldStage(2, 2);

    // fragment addressing: warp (wm, wn), tile 64x64
    const int wm = wid & 1, wn = wid >> 1;
    const int l15 = lid & 15, h = lid >> 4;
    uint32_t aoff[4]; int ax[4];
#pragma unroll
    for (int i = 0; i < 4; i++) {
        const int r = wm * 64 + i * 16 + l15;
        aoff[i] = r * 64; ax[i] = (r >> 1) & 3;
    }
    uint32_t boff[4]; int bx[4];
#pragma unroll
    for (int g = 0; g < 4; g++) {
        const int r = wn * 64 + g * 16 + l15;
        boff[g] = r * 64; bx[g] = (r >> 1) & 3;
    }

    float acc[4][8][4];
#pragma unroll
    for (int i = 0; i < 4; i++)
#pragma unroll
        for (int j = 0; j < 8; j++)
#pragma unroll
            for (int k = 0; k < 4; k++) acc[i][j][k] = 0.f;

    for (int t = 0; t < nT; t++) {
        const int remain = nT - 1 - t;
        if (remain >= 2)      asm volatile("cp.async.wait_group 2;" ::: "memory");
        else if (remain == 1) asm volatile("cp.async.wait_group 1;" ::: "memory");
        else                  asm volatile("cp.async.wait_group 0;" ::: "memory");
        __syncthreads();
        if (t + 3 < nT) ldStage((t + 3) & 3, t + 3);

        const int slot = t & 3;
        const uint32_t aB = sb + slot * ASTG;
        const uint32_t bB = sb + BOFF + slot * BSTG;
#pragma unroll
        for (int s = 0; s < 2; s++) {
            uint32_t af[4][4], bfr[4][4];
            const int jb = 2 * s + h;
#pragma unroll
            for (int i = 0; i < 4; i++)
                ldm4(af[i], aB + aoff[i] + (uint32_t)((jb ^ ax[i]) << 4));
#pragma unroll
            for (int g = 0; g < 4; g++)
                ldm4(bfr[g], bB + boff[g] + (uint32_t)((jb ^ bx[g]) << 4));
#pragma unroll
            for (int mi = 0; mi < 4; mi++)
#pragma unroll
                for (int g = 0; g < 4; g++) {
                    mma_op<DT>(acc[mi][2 * g],     af[mi], bfr[g][0], bfr[g][2]);
                    mma_op<DT>(acc[mi][2 * g + 1], af[mi], bfr[g][1], bfr[g][3]);
                }
        }
    }

    // epilogue
    const long long rowBase = (long long)blockIdx.z * cBatchRows + cRowOff + bm0 + wm * 64;
    const int colW = (int)bn0 + wn * 64;
#pragma unroll
    for (int mi = 0; mi < 4; mi++) {
        const long long r0 = rowBase + mi * 16 + (lid >> 2);
        const long long r1 = r0 + 8;
#pragma unroll
        for (int nj = 0; nj < 8; nj++) {
            const int col = colW + nj * 8 + (lid & 3) * 2;
            float b0 = 0.f, b1 = 0.f;
            if (bias) { b0 = bias[col]; b1 = bias[col + 1]; }
            const float v00 = acc[mi][nj][0] + b0, v01 = acc[mi][nj][1] + b1;
            const float v10 = acc[mi][nj][2] + b0, v11 = acc[mi][nj][3] + b1;
            if (C) {
                *(float2*)&C[r0 * N + col] = make_float2(v00, v01);
                *(float2*)&C[r1 * N + col] = make_float2(v10, v11);
            }
            if (sA3) {
                unsigned short h0 = bf16bits(v00), h1 = bf16bits(v01);
                ushort2 H = { h0, h1 };
                ushort2 L = { bf16bits(v00 - bf16val(h0)), bf16bits(v01 - bf16val(h1)) };
                unsigned short* sr = (unsigned short*)(sA3 + r0 * (3LL * N));
                *(ushort2*)(sr + col) = H;
                *(ushort2*)(sr + N + col) = H;
                *(ushort2*)(sr + 2LL * N + col) = L;
                h0 = bf16bits(v10); h1 = bf16bits(v11);
                H = { h0, h1 };
                L = { bf16bits(v10 - bf16val(h0)), bf16bits(v11 - bf16val(h1)) };
                sr = (unsigned short*)(sA3 + r1 * (3LL * N));
                *(ushort2*)(sr + col) = H;
                *(ushort2*)(sr + N + col) = H;
                *(ushort2*)(sr + 2LL * N + col) = L;
            }
            if (sH) {
                *(__half2*)&sH[r0 * N + col] = __floats2half2_rn(v00, v01);
                *(__half2*)&sH[r1 * N + col] = __floats2half2_rn(v10, v11);
            }
        }
    }
}

// ======================= split / convert / transpose kernels =================
template<bool BSPLIT>
__global__ void split_rows(const float* __restrict__ in, __nv_bfloat16* __restrict__ out,
                           long long R, int K)
{
    const long long total = R * (long long)(K >> 2);
    const int K4 = K >> 2;
    for (long long i = (long long)blockIdx.x * blockDim.x + threadIdx.x;
         i < total; i += (long long)gridDim.x * blockDim.x) {
        const long long r = i / K4;
        const int k = (int)(i - r * K4) << 2;
        const float4 v = ((const float4*)in)[i];
        ushort4 H, L;
        H.x = bf16bits(v.x); L.x = bf16bits(v.x - bf16val(H.x));
        H.y = bf16bits(v.y); L.y = bf16bits(v.y - bf16val(H.y));
        H.z = bf16bits(v.z); L.z = bf16bits(v.z - bf16val(H.z));
        H.w = bf16bits(v.w); L.w = bf16bits(v.w - bf16val(H.w));
        unsigned short* row = (unsigned short*)(out + r * (3LL * K));
        *(ushort4*)(row + k) = H;
        if (BSPLIT) { *(ushort4*)(row + K + k) = L; *(ushort4*)(row + 2 * K + k) = H; }
        else        { *(ushort4*)(row + K + k) = H; *(ushort4*)(row + 2 * K + k) = L; }
    }
}

__global__ void transpose_split(const float* __restrict__ in, __nv_bfloat16* __restrict__ out,
                                int Kd, int Nd)
{
    __shared__ float tile[32][33];
    const int k0 = blockIdx.y * 32, n0 = blockIdx.x * 32;
    for (int i = threadIdx.y; i < 32; i += 8)
        tile[i][threadIdx.x] = in[(long long)(k0 + i) * Nd + n0 + threadIdx.x];
    __syncthreads();
    for (int i = threadIdx.y; i < 32; i += 8) {
        const int n = n0 + i, k = k0 + threadIdx.x;
        const float v = tile[threadIdx.x][i];
        const unsigned short hb = bf16bits(v);
        const unsigned short lb = bf16bits(v - bf16val(hb));
        unsigned short* row = (unsigned short*)(out + (long long)n * (3LL * Kd));
        row[k] = hb; row[Kd + k] = lb; row[2 * Kd + k] = hb;
    }
}

__global__ void transpose_h(const float* __restrict__ in, __half* __restrict__ out,
                            int Kd, int Nd, long long inBatch, long long outBatch)
{
    __shared__ float tile[32][33];
    in  += (long long)blockIdx.z * inBatch;
    out += (long long)blockIdx.z * outBatch;
    const int k0 = blockIdx.y * 32, n0 = blockIdx.x * 32;
    for (int i = threadIdx.y; i < 32; i += 8)
        tile[i][threadIdx.x] = in[(long long)(k0 + i) * Nd + n0 + threadIdx.x];
    __syncthreads();
    for (int i = threadIdx.y; i < 32; i += 8) {
        const int n = n0 + i, k = k0 + threadIdx.x;
        out[(long long)n * Kd + k] = __float2half_rn(tile[threadIdx.x][i]);
    }
}

__global__ void cvt_half(const float* __restrict__ in, __half* __restrict__ out, long long n4)
{
    for (long long i = (long long)blockIdx.x * blockDim.x + threadIdx.x;
         i < n4; i += (long long)gridDim.x * blockDim.x) {
        const float4 v = ((const float4*)in)[i];
        ((__half2*)out)[2 * i]     = __floats2half2_rn(v.x, v.y);
        ((__half2*)out)[2 * i + 1] = __floats2half2_rn(v.z, v.w);
    }
}

// ======================= softmax over QUERY axis -> fp16 =====================
__global__ void softmax_h(float* __restrict__ s, __half* __restrict__ attnh)
{
    const int col = blockIdx.x * blockDim.x + threadIdx.x;
    const int b = blockIdx.y;
    float* base = s + (long long)b * SQ * KVLEN + col;
    float mx = -1e30f;
    for (int r = 0; r < SQ; r++) mx = fmaxf(mx, base[(long long)r * KVLEN]);
    float sum = 0.f;
    for (int r = 0; r < SQ; r++) {
        const long long idx = (long long)r * KVLEN;
        const float e = __expf(base[idx] - mx);
        base[idx] = e;
        sum += e;
    }
    const float inv = 1.f / sum;
    __half* a = attnh + (long long)b * SQ * KVLEN + col;
    for (int r = 0; r < SQ; r++)
        a[(long long)r * KVLEN] = __float2half_rn(base[(long long)r * KVLEN] * inv);
}

// ======================= KV cache copy =======================================
__global__ void cache_copy(const float* __restrict__ kc, const float* __restrict__ vc,
                           float* __restrict__ kout, float* __restrict__ vout)
{
    const long long per = (long long)PAST * DH / 4;
    const long long tot = per * NB;
    for (long long i = (long long)blockIdx.x * blockDim.x + threadIdx.x;
         i < tot; i += (long long)gridDim.x * blockDim.x) {
        const int b = (int)(i / per);
        const long long o = i - (long long)b * per;
        const long long dst = (long long)b * ((long long)KVLEN * DH / 4) + o;
        ((float4*)kout)[dst] = ((const float4*)kc)[i];
        ((float4*)vout)[dst] = ((const float4*)vc)[i];
    }
}

// =============================================================================
extern "C" void kernel_launch(void* const* d_in, const int* in_sizes, int n_in,
                              void* d_out, int out_size)
{
    const float* x    = (const float*)d_in[0];
    const float* kc   = (const float*)d_in[1];
    const float* vc   = (const float*)d_in[2];
    const float* Wq   = (const float*)d_in[3];
    const float* bq   = (const float*)d_in[4];
    const float* Wk   = (const float*)d_in[5];
    const float* bk   = (const float*)d_in[6];
    const float* Wv   = (const float*)d_in[7];
    const float* bv   = (const float*)d_in[8];
    const float* Wff  = (const float*)d_in[9];
    const float* bff  = (const float*)d_in[10];
    const float* Wout = (const float*)d_in[11];
    const float* bout = (const float*)d_in[12];

    float* out  = (float*)d_out;
    float* kout = out  + (long long)NB * SQ * DH;
    float* vout = kout + (long long)NB * KVLEN * DH;

    void* p;
    cudaGetSymbolAddress(&p, g_scores); float* scores = (float*)p;
    cudaGetSymbolAddress(&p, g_xs);    __nv_bfloat16* xs  = (__nv_bfloat16*)p;
    cudaGetSymbolAddress(&p, g_qs);    __nv_bfloat16* qs  = (__nv_bfloat16*)p;
    cudaGetSymbolAddress(&p, g_ks);    __nv_bfloat16* ks  = (__nv_bfloat16*)p;
    cudaGetSymbolAddress(&p, g_wqs);   __nv_bfloat16* wqs = (__nv_bfloat16*)p;
    cudaGetSymbolAddress(&p, g_wks);   __nv_bfloat16* wks = (__nv_bfloat16*)p;
    cudaGetSymbolAddress(&p, g_xh);    __half* xh    = (__half*)p;
    cudaGetSymbolAddress(&p, g_wvh);   __half* wvh   = (__half*)p;
    cudaGetSymbolAddress(&p, g_wffh);  __half* wffh  = (__half*)p;
    cudaGetSymbolAddress(&p, g_wouth); __half* wouth = (__half*)p;
    cudaGetSymbolAddress(&p, g_vth);   __half* vth   = (__half*)p;
    cudaGetSymbolAddress(&p, g_attnh); __half* attnh = (__half*)p;
    cudaGetSymbolAddress(&p, g_ctxh);  __half* ctxh  = (__half*)p;
    cudaGetSymbolAddress(&p, g_ffh);   __half* ffh   = (__half*)p;

    cudaFuncSetAttribute(gemm_tc<0>, cudaFuncAttributeMaxDynamicSharedMemorySize, SMEM_GEMM);
    cudaFuncSetAttribute(gemm_tc<1>, cudaFuncAttributeMaxDynamicSharedMemorySize, SMEM_GEMM);

    dim3 t32x8(32, 8);
    const int M = NB * SQ;  // 8192

    // 0) operand prep
    split_rows<false><<<2048, 256>>>(x, xs, (long long)M, DIN);
    cvt_half<<<2048, 256>>>(x, xh, (long long)M * DIN / 4);
    transpose_split<<<dim3(DH / 32, DIN / 32, 1), t32x8>>>(Wq, wqs, DIN, DH);
    transpose_split<<<dim3(DH / 32, DIN / 32, 1), t32x8>>>(Wk, wks, DIN, DH);
    transpose_h<<<dim3(DH / 32, DIN / 32, 1), t32x8>>>(Wv, wvh, DIN, DH, 0, 0);
    transpose_h<<<dim3(DFF / 32, DH / 32, 1), t32x8>>>(Wff, wffh, DH, DFF, 0, 0);
    transpose_h<<<dim3(DH / 32, DFF / 32, 1), t32x8>>>(Wout, wouth, DFF, DH, 0, 0);
    cache_copy<<<2048, 256>>>(kc, vc, kout, vout);

    // 1) projections: q,k bf16x3 (K'=6144); v plain fp16 (K=2048)
    gemm_tc<0><<<dim3(DH / 256, M / 128, 1), 256, SMEM_GEMM>>>(
        (const uint16_t*)xs, (const uint16_t*)wqs, bq, nullptr, qs, nullptr,
        DH, 3 * DIN, 0, 0, M, 0);
    gemm_tc<0><<<dim3(DH / 256, SQ / 128, NB), 256, SMEM_GEMM>>>(
        (const uint16_t*)xs, (const uint16_t*)wks, bk, kout, nullptr, nullptr,
        DH, 3 * DIN, (long long)SQ * 3 * DIN, 0, KVLEN, PAST);
    gemm_tc<1><<<dim3(DH / 256, SQ / 128, NB), 256, SMEM_GEMM>>>(
        (const uint16_t*)xh, (const uint16_t*)wvh, bv, vout, nullptr, nullptr,
        DH, DIN, (long long)SQ * DIN, 0, KVLEN, PAST);

    // 2) K cache -> bf16 B-split; V cache -> fp16 transpose
    split_rows<true><<<2048, 256>>>(kout, ks, (long long)NB * KVLEN, DH);
    transpose_h<<<dim3(DH / 32, KVLEN / 32, NB), t32x8>>>(
        vout, vth, KVLEN, DH, (long long)KVLEN * DH, (long long)DH * KVLEN);

    // 3) scores = q' @ k'^T  (bf16x3, K'=6144)
    gemm_tc<0><<<dim3(KVLEN / 256, SQ / 128, NB), 256, SMEM_GEMM>>>(
        (const uint16_t*)qs, (const uint16_t*)ks, nullptr, scores, nullptr, nullptr,
        KVLEN, 3 * DH, (long long)SQ * 3 * DH, (long long)KVLEN * 3 * DH, SQ, 0);

    // 4) softmax over query axis -> fp16 attn
    softmax_h<<<dim3(KVLEN / 256, NB), 256>>>(scores, attnh);

    // 5) ctx = attn @ v  (fp16, K=4096) -> fp16 ctx
    gemm_tc<1><<<dim3(DH / 256, SQ / 128, NB), 256, SMEM_GEMM>>>(
        (const uint16_t*)attnh, (const uint16_t*)vth, nullptr, nullptr, nullptr, ctxh,
        DH, KVLEN, (long long)SQ * KVLEN, (long long)DH * KVLEN, SQ, 0);

    // 6) FFN (fp16): ff = ctx @ Wff^T + bff ; out = ff @ Wout^T + bout
    gemm_tc<1><<<dim3(DFF / 256, M / 128, 1), 256, SMEM_GEMM>>>(
        (const uint16_t*)ctxh, (const uint16_t*)wffh, bff, nullptr, nullptr, ffh,
        DFF, DH, 0, 0, M, 0);
    gemm_tc<1><<<dim3(DH / 256, M / 128, 1), 256, SMEM_GEMM>>>(
        (const uint16_t*)ffh, (const uint16_t*)wouth, bout, out, nullptr, nullptr,
        DH, DFF, 0, 0, M, 0);
}

// round 8
// speedup vs baseline: 1.1162x; 1.1162x over previous
#include <cuda_runtime.h>
#include <cuda_bf16.h>
#include <cuda_fp16.h>
#include <cstdint>

#define NB    4
#define SQ    2048
#define PAST  2048
#define DIN   2048
#define DH    2048
#define DFF   8192
#define KVLEN (PAST + SQ)   // 4096

// ======================= device scratch (no allocation) ======================
__device__ float g_scores[(long long)NB * SQ * KVLEN];
__device__ __nv_bfloat16 g_xs [(long long)NB*SQ * 3*DIN];
__device__ __nv_bfloat16 g_qs [(long long)NB*SQ * 3*DH];
__device__ __nv_bfloat16 g_ks [(long long)NB*KVLEN * 3*DH];
__device__ __nv_bfloat16 g_wqs[(long long)DH * 3*DIN];
__device__ __nv_bfloat16 g_wks[(long long)DH * 3*DIN];
__device__ __half g_xh   [(long long)NB*SQ * DIN];
__device__ __half g_wvh  [(long long)DH * DIN];
__device__ __half g_wffh [(long long)DFF * DH];
__device__ __half g_wouth[(long long)DH * DFF];
__device__ __half g_vth  [(long long)NB * DH * KVLEN];
__device__ __half g_attnh[(long long)NB * SQ * KVLEN];
__device__ __half g_ctxh [(long long)NB * SQ * DH];
__device__ __half g_ffh  [(long long)NB * SQ * DFF];

// ======================= helpers =============================================
__device__ __forceinline__ uint32_t smem_u32(const void* p) {
    uint32_t a;
    asm("{ .reg .u64 t; cvta.to.shared.u64 t, %1; cvt.u32.u64 %0, t; }" : "=r"(a) : "l"(p));
    return a;
}
__device__ __forceinline__ void ldm4(uint32_t* f, uint32_t a) {
    asm volatile("ldmatrix.sync.aligned.m8n8.x4.shared.b16 {%0,%1,%2,%3}, [%4];"
                 : "=r"(f[0]), "=r"(f[1]), "=r"(f[2]), "=r"(f[3]) : "r"(a));
}
template<int DT>   // 0 = bf16, 1 = f16
__device__ __forceinline__ void mma_op(float* c, const uint32_t* a, uint32_t b0, uint32_t b1) {
    if (DT == 0)
        asm volatile("mma.sync.aligned.m16n8k16.row.col.f32.bf16.bf16.f32 "
                     "{%0,%1,%2,%3}, {%4,%5,%6,%7}, {%8,%9}, {%0,%1,%2,%3};"
                     : "+f"(c[0]), "+f"(c[1]), "+f"(c[2]), "+f"(c[3])
                     : "r"(a[0]), "r"(a[1]), "r"(a[2]), "r"(a[3]), "r"(b0), "r"(b1));
    else
        asm volatile("mma.sync.aligned.m16n8k16.row.col.f32.f16.f16.f32 "
                     "{%0,%1,%2,%3}, {%4,%5,%6,%7}, {%8,%9}, {%0,%1,%2,%3};"
                     : "+f"(c[0]), "+f"(c[1]), "+f"(c[2]), "+f"(c[3])
                     : "r"(a[0]), "r"(a[1]), "r"(a[2]), "r"(a[3]), "r"(b0), "r"(b1));
}
__device__ __forceinline__ unsigned short bf16bits(float f) {
    __nv_bfloat16 h = __float2bfloat16(f);
    return *reinterpret_cast<unsigned short*>(&h);
}
__device__ __forceinline__ float bf16val(unsigned short u) {
    __nv_bfloat16 h = *reinterpret_cast<__nv_bfloat16*>(&u);
    return __bfloat162float(h);
}
__device__ __forceinline__ uint32_t swz(int r, int j) {   // 16B seg j in 64B row r
    return (uint32_t)(r * 64 + ((j ^ ((r >> 1) & 3)) << 4));
}
#define CP16(dst, src) asm volatile("cp.async.ca.shared.global [%0], [%1], 16;" :: "r"(dst), "l"(src) : "memory")
#define CP_COMMIT()    asm volatile("cp.async.commit_group;" ::: "memory")

// ======================= GEMM: C[M,N] = A[M,K]·B[N,K]^T =====================
// CTA tile 128x128x32, 128 threads = 4 warps (2M x 2N), warp tile 64x64.
// 3-stage cp.async, static smem 48KB -> 2 CTAs/SM.
// Outputs (nullable): C fp32; sA3 bf16 (hi,hi,lo) stride 3N; sH fp16 stride N.
template<int DT>
__global__ void __launch_bounds__(128, 2)
gemm_tc(const uint16_t* __restrict__ A, const uint16_t* __restrict__ B,
        const float* __restrict__ bias, float* __restrict__ C,
        __nv_bfloat16* __restrict__ sA3, __half* __restrict__ sH,
        int N, long long Kp,
        long long aBatch, long long bBatch,
        int cBatchRows, int cRowOff)
{
    __shared__ __align__(16) uint8_t As[3][8192];
    __shared__ __align__(16) uint8_t Bs[3][8192];

    const int tid = threadIdx.x;
    const int wid = tid >> 5;
    const int lid = tid & 31;
    const long long bn0 = (long long)blockIdx.x * 128;
    const long long bm0 = (long long)blockIdx.y * 128;

    A += (long long)blockIdx.z * aBatch + bm0 * Kp;
    B += (long long)blockIdx.z * bBatch + bn0 * Kp;

    // loaders: 512 segs per operand, 4 per thread (128 threads)
    const uint16_t* aG[4];
    const uint16_t* bG[4];
    uint32_t sa[4];
#pragma unroll
    for (int i = 0; i < 4; i++) {
        const int u = tid + i * 128;
        const int r = u >> 2, j = u & 3;
        aG[i] = A + (long long)r * Kp + j * 8;
        bG[i] = B + (long long)r * Kp + j * 8;
        sa[i] = swz(r, j);
    }
    const uint32_t aSm = smem_u32(As), bSm = smem_u32(Bs);

    const int nT = (int)(Kp >> 5);

    auto ldStage = [&](int slot, int chunk) {
        const long long o = (long long)chunk * 32;
        const uint32_t ab = aSm + slot * 8192;
        const uint32_t bb = bSm + slot * 8192;
#pragma unroll
        for (int i = 0; i < 4; i++) CP16(ab + sa[i], aG[i] + o);
#pragma unroll
        for (int i = 0; i < 4; i++) CP16(bb + sa[i], bG[i] + o);
        CP_COMMIT();
    };
    ldStage(0, 0);
    ldStage(1, 1);

    // fragment addressing: warp (wm, wn), tile 64x64
    const int wm = wid & 1, wn = wid >> 1;
    const int l15 = lid & 15, h = lid >> 4;
    uint32_t aoff[4]; int ax[4];
#pragma unroll
    for (int i = 0; i < 4; i++) {
        const int r = wm * 64 + i * 16 + l15;
        aoff[i] = r * 64; ax[i] = (r >> 1) & 3;
    }
    uint32_t boff[4]; int bx[4];
#pragma unroll
    for (int g = 0; g < 4; g++) {
        const int r = wn * 64 + g * 16 + l15;
        boff[g] = r * 64; bx[g] = (r >> 1) & 3;
    }

    float acc[4][8][4];
#pragma unroll
    for (int i = 0; i < 4; i++)
#pragma unroll
        for (int j = 0; j < 8; j++)
#pragma unroll
            for (int k = 0; k < 4; k++) acc[i][j][k] = 0.f;

    for (int t = 0; t < nT; t++) {
        if (t + 1 < nT) asm volatile("cp.async.wait_group 1;" ::: "memory");
        else            asm volatile("cp.async.wait_group 0;" ::: "memory");
        __syncthreads();
        if (t + 2 < nT) ldStage((t + 2) % 3, t + 2);

        const int slot = t % 3;
        const uint32_t aB = aSm + slot * 8192;
        const uint32_t bB = bSm + slot * 8192;
#pragma unroll
        for (int s = 0; s < 2; s++) {
            uint32_t af[4][4], bfr[4][4];
            const int jb = 2 * s + h;
#pragma unroll
            for (int i = 0; i < 4; i++)
                ldm4(af[i], aB + aoff[i] + (uint32_t)((jb ^ ax[i]) << 4));
#pragma unroll
            for (int g = 0; g < 4; g++)
                ldm4(bfr[g], bB + boff[g] + (uint32_t)((jb ^ bx[g]) << 4));
#pragma unroll
            for (int mi = 0; mi < 4; mi++)
#pragma unroll
                for (int g = 0; g < 4; g++) {
                    mma_op<DT>(acc[mi][2 * g],     af[mi], bfr[g][0], bfr[g][2]);
                    mma_op<DT>(acc[mi][2 * g + 1], af[mi], bfr[g][1], bfr[g][3]);
                }
        }
    }

    // epilogue
    const long long rowBase = (long long)blockIdx.z * cBatchRows + cRowOff + bm0 + wm * 64;
    const int colW = (int)bn0 + wn * 64;
#pragma unroll
    for (int mi = 0; mi < 4; mi++) {
        const long long r0 = rowBase + mi * 16 + (lid >> 2);
        const long long r1 = r0 + 8;
#pragma unroll
        for (int nj = 0; nj < 8; nj++) {
            const int col = colW + nj * 8 + (lid & 3) * 2;
            float b0 = 0.f, b1 = 0.f;
            if (bias) { b0 = bias[col]; b1 = bias[col + 1]; }
            const float v00 = acc[mi][nj][0] + b0, v01 = acc[mi][nj][1] + b1;
            const float v10 = acc[mi][nj][2] + b0, v11 = acc[mi][nj][3] + b1;
            if (C) {
                *(float2*)&C[r0 * N + col] = make_float2(v00, v01);
                *(float2*)&C[r1 * N + col] = make_float2(v10, v11);
            }
            if (sA3) {
                unsigned short h0 = bf16bits(v00), h1 = bf16bits(v01);
                ushort2 H = { h0, h1 };
                ushort2 L = { bf16bits(v00 - bf16val(h0)), bf16bits(v01 - bf16val(h1)) };
                unsigned short* sr = (unsigned short*)(sA3 + r0 * (3LL * N));
                *(ushort2*)(sr + col) = H;
                *(ushort2*)(sr + N + col) = H;
                *(ushort2*)(sr + 2LL * N + col) = L;
                h0 = bf16bits(v10); h1 = bf16bits(v11);
                H = { h0, h1 };
                L = { bf16bits(v10 - bf16val(h0)), bf16bits(v11 - bf16val(h1)) };
                sr = (unsigned short*)(sA3 + r1 * (3LL * N));
                *(ushort2*)(sr + col) = H;
                *(ushort2*)(sr + N + col) = H;
                *(ushort2*)(sr + 2LL * N + col) = L;
            }
            if (sH) {
                *(__half2*)&sH[r0 * N + col] = __floats2half2_rn(v00, v01);
                *(__half2*)&sH[r1 * N + col] = __floats2half2_rn(v10, v11);
            }
        }
    }
}

// ======================= split / convert / transpose kernels =================
// Fused: x -> xs (hi,hi,lo 3-seg bf16) AND xh (fp16), single read of x.
__global__ void split_cvt_x(const float* __restrict__ in, __nv_bfloat16* __restrict__ out3,
                            __half* __restrict__ outh, long long R, int K)
{
    const long long total = R * (long long)(K >> 2);
    const int K4 = K >> 2;
    for (long long i = (long long)blockIdx.x * blockDim.x + threadIdx.x;
         i < total; i += (long long)gridDim.x * blockDim.x) {
        const long long r = i / K4;
        const int k = (int)(i - r * K4) << 2;
        const float4 v = ((const float4*)in)[i];
        ushort4 H, L;
        H.x = bf16bits(v.x); L.x = bf16bits(v.x - bf16val(H.x));
        H.y = bf16bits(v.y); L.y = bf16bits(v.y - bf16val(H.y));
        H.z = bf16bits(v.z); L.z = bf16bits(v.z - bf16val(H.z));
        H.w = bf16bits(v.w); L.w = bf16bits(v.w - bf16val(H.w));
        unsigned short* row = (unsigned short*)(out3 + r * (3LL * K));
        *(ushort4*)(row + k) = H;
        *(ushort4*)(row + K + k) = H;
        *(ushort4*)(row + 2 * K + k) = L;
        __half2 h01 = __floats2half2_rn(v.x, v.y);
        __half2 h23 = __floats2half2_rn(v.z, v.w);
        __half2* ho = (__half2*)(outh + r * (long long)K + k);
        ho[0] = h01; ho[1] = h23;
    }
}

// B-operand split (hi,lo,hi)
__global__ void split_rows_b(const float* __restrict__ in, __nv_bfloat16* __restrict__ out,
                             long long R, int K)
{
    const long long total = R * (long long)(K >> 2);
    const int K4 = K >> 2;
    for (long long i = (long long)blockIdx.x * blockDim.x + threadIdx.x;
         i < total; i += (long long)gridDim.x * blockDim.x) {
        const long long r = i / K4;
        const int k = (int)(i - r * K4) << 2;
        const float4 v = ((const float4*)in)[i];
        ushort4 H, L;
        H.x = bf16bits(v.x); L.x = bf16bits(v.x - bf16val(H.x));
        H.y = bf16bits(v.y); L.y = bf16bits(v.y - bf16val(H.y));
        H.z = bf16bits(v.z); L.z = bf16bits(v.z - bf16val(H.z));
        H.w = bf16bits(v.w); L.w = bf16bits(v.w - bf16val(H.w));
        unsigned short* row = (unsigned short*)(out + r * (3LL * K));
        *(ushort4*)(row + k) = H;
        *(ushort4*)(row + K + k) = L;
        *(ushort4*)(row + 2 * K + k) = H;
    }
}

__global__ void transpose_split(const float* __restrict__ in, __nv_bfloat16* __restrict__ out,
                                int Kd, int Nd)
{
    __shared__ float tile[32][33];
    const int k0 = blockIdx.y * 32, n0 = blockIdx.x * 32;
    for (int i = threadIdx.y; i < 32; i += 8)
        tile[i][threadIdx.x] = in[(long long)(k0 + i) * Nd + n0 + threadIdx.x];
    __syncthreads();
    for (int i = threadIdx.y; i < 32; i += 8) {
        const int n = n0 + i, k = k0 + threadIdx.x;
        const float v = tile[threadIdx.x][i];
        const unsigned short hb = bf16bits(v);
        const unsigned short lb = bf16bits(v - bf16val(hb));
        unsigned short* row = (unsigned short*)(out + (long long)n * (3LL * Kd));
        row[k] = hb; row[Kd + k] = lb; row[2 * Kd + k] = hb;
    }
}

__global__ void transpose_h(const float* __restrict__ in, __half* __restrict__ out,
                            int Kd, int Nd, long long inBatch, long long outBatch)
{
    __shared__ float tile[32][33];
    in  += (long long)blockIdx.z * inBatch;
    out += (long long)blockIdx.z * outBatch;
    const int k0 = blockIdx.y * 32, n0 = blockIdx.x * 32;
    for (int i = threadIdx.y; i < 32; i += 8)
        tile[i][threadIdx.x] = in[(long long)(k0 + i) * Nd + n0 + threadIdx.x];
    __syncthreads();
    for (int i = threadIdx.y; i < 32; i += 8) {
        const int n = n0 + i, k = k0 + threadIdx.x;
        out[(long long)n * Kd + k] = __float2half_rn(tile[threadIdx.x][i]);
    }
}

// ======================= softmax over QUERY axis -> fp16 =====================
__global__ void softmax_h(float* __restrict__ s, __half* __restrict__ attnh)
{
    const int col = blockIdx.x * blockDim.x + threadIdx.x;
    const int b = blockIdx.y;
    float* base = s + (long long)b * SQ * KVLEN + col;
    float mx = -1e30f;
    for (int r = 0; r < SQ; r++) mx = fmaxf(mx, base[(long long)r * KVLEN]);
    float sum = 0.f;
    for (int r = 0; r < SQ; r++) {
        const long long idx = (long long)r * KVLEN;
        const float e = __expf(base[idx] - mx);
        base[idx] = e;
        sum += e;
    }
    const float inv = 1.f / sum;
    __half* a = attnh + (long long)b * SQ * KVLEN + col;
    for (int r = 0; r < SQ; r++)
        a[(long long)r * KVLEN] = __float2half_rn(base[(long long)r * KVLEN] * inv);
}

// ======================= KV cache copy =======================================
__global__ void cache_copy(const float* __restrict__ kc, const float* __restrict__ vc,
                           float* __restrict__ kout, float* __restrict__ vout)
{
    const long long per = (long long)PAST * DH / 4;
    const long long tot = per * NB;
    for (long long i = (long long)blockIdx.x * blockDim.x + threadIdx.x;
         i < tot; i += (long long)gridDim.x * blockDim.x) {
        const int b = (int)(i / per);
        const long long o = i - (long long)b * per;
        const long long dst = (long long)b * ((long long)KVLEN * DH / 4) + o;
        ((float4*)kout)[dst] = ((const float4*)kc)[i];
        ((float4*)vout)[dst] = ((const float4*)vc)[i];
    }
}

// =============================================================================
extern "C" void kernel_launch(void* const* d_in, const int* in_sizes, int n_in,
                              void* d_out, int out_size)
{
    const float* x    = (const float*)d_in[0];
    const float* kc   = (const float*)d_in[1];
    const float* vc   = (const float*)d_in[2];
    const float* Wq   = (const float*)d_in[3];
    const float* bq   = (const float*)d_in[4];
    const float* Wk   = (const float*)d_in[5];
    const float* bk   = (const float*)d_in[6];
    const float* Wv   = (const float*)d_in[7];
    const float* bv   = (const float*)d_in[8];
    const float* Wff  = (const float*)d_in[9];
    const float* bff  = (const float*)d_in[10];
    const float* Wout = (const float*)d_in[11];
    const float* bout = (const float*)d_in[12];

    float* out  = (float*)d_out;
    float* kout = out  + (long long)NB * SQ * DH;
    float* vout = kout + (long long)NB * KVLEN * DH;

    void* p;
    cudaGetSymbolAddress(&p, g_scores); float* scores = (float*)p;
    cudaGetSymbolAddress(&p, g_xs);    __nv_bfloat16* xs  = (__nv_bfloat16*)p;
    cudaGetSymbolAddress(&p, g_qs);    __nv_bfloat16* qs  = (__nv_bfloat16*)p;
    cudaGetSymbolAddress(&p, g_ks);    __nv_bfloat16* ks  = (__nv_bfloat16*)p;
    cudaGetSymbolAddress(&p, g_wqs);   __nv_bfloat16* wqs = (__nv_bfloat16*)p;
    cudaGetSymbolAddress(&p, g_wks);   __nv_bfloat16* wks = (__nv_bfloat16*)p;
    cudaGetSymbolAddress(&p, g_xh);    __half* xh    = (__half*)p;
    cudaGetSymbolAddress(&p, g_wvh);   __half* wvh   = (__half*)p;
    cudaGetSymbolAddress(&p, g_wffh);  __half* wffh  = (__half*)p;
    cudaGetSymbolAddress(&p, g_wouth); __half* wouth = (__half*)p;
    cudaGetSymbolAddress(&p, g_vth);   __half* vth   = (__half*)p;
    cudaGetSymbolAddress(&p, g_attnh); __half* attnh = (__half*)p;
    cudaGetSymbolAddress(&p, g_ctxh);  __half* ctxh  = (__half*)p;
    cudaGetSymbolAddress(&p, g_ffh);   __half* ffh   = (__half*)p;

    dim3 t32x8(32, 8);
    const int M = NB * SQ;  // 8192

    // 0) operand prep
    split_cvt_x<<<2048, 256>>>(x, xs, xh, (long long)M, DIN);
    transpose_split<<<dim3(DH / 32, DIN / 32, 1), t32x8>>>(Wq, wqs, DIN, DH);
    transpose_split<<<dim3(DH / 32, DIN / 32, 1), t32x8>>>(Wk, wks, DIN, DH);
    transpose_h<<<dim3(DH / 32, DIN / 32, 1), t32x8>>>(Wv, wvh, DIN, DH, 0, 0);
    transpose_h<<<dim3(DFF / 32, DH / 32, 1), t32x8>>>(Wff, wffh, DH, DFF, 0, 0);
    transpose_h<<<dim3(DH / 32, DFF / 32, 1), t32x8>>>(Wout, wouth, DFF, DH, 0, 0);
    cache_copy<<<2048, 256>>>(kc, vc, kout, vout);

    // 1) projections: q,k bf16x3 (K'=6144); v plain fp16 (K=2048)
    gemm_tc<0><<<dim3(DH / 128, M / 128, 1), 128>>>(
        (const uint16_t*)xs, (const uint16_t*)wqs, bq, nullptr, qs, nullptr,
        DH, 3 * DIN, 0, 0, M, 0);
    gemm_tc<0><<<dim3(DH / 128, SQ / 128, NB), 128>>>(
        (const uint16_t*)xs, (const uint16_t*)wks, bk, kout, nullptr, nullptr,
        DH, 3 * DIN, (long long)SQ * 3 * DIN, 0, KVLEN, PAST);
    gemm_tc<1><<<dim3(DH / 128, SQ / 128, NB), 128>>>(
        (const uint16_t*)xh, (const uint16_t*)wvh, bv, vout, nullptr, nullptr,
        DH, DIN, (long long)SQ * DIN, 0, KVLEN, PAST);

    // 2) K cache -> bf16 B-split; V cache -> fp16 transpose
    split_rows_b<<<2048, 256>>>(kout, ks, (long long)NB * KVLEN, DH);
    transpose_h<<<dim3(DH / 32, KVLEN / 32, NB), t32x8>>>(
        vout, vth, KVLEN, DH, (long long)KVLEN * DH, (long long)DH * KVLEN);

    // 3) scores = q' @ k'^T  (bf16x3, K'=6144)
    gemm_tc<0><<<dim3(KVLEN / 128, SQ / 128, NB), 128>>>(
        (const uint16_t*)qs, (const uint16_t*)ks, nullptr, scores, nullptr, nullptr,
        KVLEN, 3 * DH, (long long)SQ * 3 * DH, (long long)KVLEN * 3 * DH, SQ, 0);

    // 4) softmax over query axis -> fp16 attn
    softmax_h<<<dim3(KVLEN / 256, NB), 256>>>(scores, attnh);

    // 5) ctx = attn @ v  (fp16, K=4096) -> fp16 ctx
    gemm_tc<1><<<dim3(DH / 128, SQ / 128, NB), 128>>>(
        (const uint16_t*)attnh, (const uint16_t*)vth, nullptr, nullptr, nullptr, ctxh,
        DH, KVLEN, (long long)SQ * KVLEN, (long long)DH * KVLEN, SQ, 0);

    // 6) FFN (fp16): ff = ctx @ Wff^T + bff ; out = ff @ Wout^T + bout
    gemm_tc<1><<<dim3(DFF / 128, M / 128, 1), 128>>>(
        (const uint16_t*)ctxh, (const uint16_t*)wffh, bff, nullptr, nullptr, ffh,
        DFF, DH, 0, 0, M, 0);
    gemm_tc<1><<<dim3(DH / 128, M / 128, 1), 128>>>(
        (const uint16_t*)ffh, (const uint16_t*)wouth, bout, out, nullptr, nullptr,
        DH, DFF, 0, 0, M, 0);
}